// round 14
// baseline (speedup 1.0000x reference)
#include <cuda_runtime.h>
#include <math.h>
#include <stdint.h>

// ---------------- problem constants ----------------
#define BATCH    512
#define NNODE    256
#define MROWS    (BATCH*NNODE)   // 131072
#define NODE_D   256
#define FEAT_IN  512
#define GLOB_D   64
#define IN_DIM   576             // FEAT_IN + GLOB_D
#define FEAT_HID 1024
#define ATTN_HID 256
#define NCOMB    1280            // FEAT_HID + ATTN_HID
#define FEAT_OUT 256
#define NHEADS   4
#define LN_EPS   1e-5f

// ---------------- scratch (static device globals; no allocation) ----------------
__device__ float g_inp[(size_t)MROWS * IN_DIM];
__device__ float g_h1[(size_t)MROWS * FEAT_HID];
__device__ float g_a1[(size_t)MROWS * ATTN_HID];
__device__ float g_feats[(size_t)MROWS * FEAT_OUT];
__device__ float g_scores[(size_t)MROWS * NHEADS];
__device__ float g_w[(size_t)MROWS * NHEADS];
__device__ float g_w1c[(size_t)IN_DIM * NCOMB];     // fw1 || aw1, tf32-rounded
__device__ float g_bc[NCOMB];                       // fb1 || ab1
__device__ float g_fw2r[(size_t)FEAT_HID * FEAT_OUT];

// ---------------- TF32 helpers ----------------
__device__ __forceinline__ uint32_t f2tf(float x) {
    uint32_t r;
    asm("cvt.rna.tf32.f32 %0, %1;" : "=r"(r) : "f"(x));
    return r;
}
__device__ __forceinline__ float f2tf_f(float x) { return __uint_as_float(f2tf(x)); }

__device__ __forceinline__ void mma_tf32(float* c, const uint32_t* a, const uint32_t* b) {
    asm volatile(
        "mma.sync.aligned.m16n8k8.row.col.f32.tf32.tf32.f32 "
        "{%0,%1,%2,%3}, {%4,%5,%6,%7}, {%8,%9}, {%0,%1,%2,%3};"
        : "+f"(c[0]), "+f"(c[1]), "+f"(c[2]), "+f"(c[3])
        : "r"(a[0]), "r"(a[1]), "r"(a[2]), "r"(a[3]), "r"(b[0]), "r"(b[1]));
}

// ---------------- cp.async helpers ----------------
__device__ __forceinline__ void cp_async16(uint32_t saddr, const void* g) {
    asm volatile("cp.async.cg.shared.global [%0], [%1], 16;" :: "r"(saddr), "l"(g));
}
__device__ __forceinline__ void cp_commit() {
    asm volatile("cp.async.commit_group;");
}
template <int N>
__device__ __forceinline__ void cp_wait() {
    asm volatile("cp.async.wait_group %0;" :: "n"(N));
}

// ---------------- stage 0a: concat + round combined weights ----------------
__global__ void concat_round_w(const float* __restrict__ fw1,
                               const float* __restrict__ aw1,
                               float* __restrict__ out) {
    int i = blockIdx.x * 256 + threadIdx.x;
    if (i >= IN_DIM * NCOMB) return;
    int k = i / NCOMB, c = i % NCOMB;
    float v = (c < FEAT_HID) ? fw1[(size_t)k * FEAT_HID + c]
                             : aw1[(size_t)k * ATTN_HID + (c - FEAT_HID)];
    out[i] = f2tf_f(v);
}

// ---------------- stage 0b: concat bias ----------------
__global__ void concat_bias(const float* __restrict__ fb1,
                            const float* __restrict__ ab1,
                            float* __restrict__ out) {
    int c = blockIdx.x * 256 + threadIdx.x;
    if (c < FEAT_HID) out[c] = fb1[c];
    else if (c < NCOMB) out[c] = ab1[c - FEAT_HID];
}

// ---------------- stage 0c: round fw2 ----------------
__global__ void round_kernel(const float* __restrict__ in, float* __restrict__ out, int n) {
    int i = blockIdx.x * blockDim.x + threadIdx.x;
    if (i < n) out[i] = f2tf_f(in[i]);
}

// ---------------- stage 1: LayerNorm(concat) + ctx concat (tf32-rounded) ----------------
__global__ void prep_kernel(const float* __restrict__ nodes,
                            const float* __restrict__ pe,
                            const float* __restrict__ globs,
                            const float* __restrict__ ln_g,
                            const float* __restrict__ ln_b) {
    int row = blockIdx.x;
    int t = threadIdx.x;        // 0..127
    int b = row >> 8;

    float4 v;
    if (t < 64) v = ((const float4*)(nodes + (size_t)row * NODE_D))[t];
    else        v = ((const float4*)(pe    + (size_t)row * NODE_D))[t - 64];

    float s  = v.x + v.y + v.z + v.w;
    float ss = v.x * v.x + v.y * v.y + v.z * v.z + v.w * v.w;
    #pragma unroll
    for (int o = 16; o; o >>= 1) {
        s  += __shfl_xor_sync(0xFFFFFFFFu, s, o);
        ss += __shfl_xor_sync(0xFFFFFFFFu, ss, o);
    }
    __shared__ float sh_s[4], sh_ss[4];
    if ((t & 31) == 0) { sh_s[t >> 5] = s; sh_ss[t >> 5] = ss; }
    __syncthreads();
    float mean = (sh_s[0] + sh_s[1] + sh_s[2] + sh_s[3]) * (1.f / 512.f);
    float m2   = (sh_ss[0] + sh_ss[1] + sh_ss[2] + sh_ss[3]) * (1.f / 512.f);
    float rstd = rsqrtf(m2 - mean * mean + LN_EPS);

    float4 g  = ((const float4*)ln_g)[t];
    float4 bt = ((const float4*)ln_b)[t];
    float4 o;
    o.x = f2tf_f((v.x - mean) * rstd * g.x + bt.x);
    o.y = f2tf_f((v.y - mean) * rstd * g.y + bt.y);
    o.z = f2tf_f((v.z - mean) * rstd * g.z + bt.z);
    o.w = f2tf_f((v.w - mean) * rstd * g.w + bt.w);
    ((float4*)(g_inp + (size_t)row * IN_DIM))[t] = o;
    if (t < 16) {
        float4 c = ((const float4*)(globs + (size_t)b * GLOB_D))[t];
        c.x = f2tf_f(c.x); c.y = f2tf_f(c.y); c.z = f2tf_f(c.z); c.w = f2tf_f(c.w);
        ((float4*)(g_inp + (size_t)row * IN_DIM + FEAT_IN))[t] = c;
    }
}

// ---------------- shared GEMM body constants ----------------
#define AST 36   // As row stride (floats), 144B, conflict-free + 16B-aligned
#define BST 136  // Bs row stride (floats), 544B
#define A_STAGE (128 * AST)
#define B_STAGE (32 * BST)
#define SMEM_FLOATS (2 * (A_STAGE + B_STAGE))
#define SMEM_BYTES (SMEM_FLOATS * 4)

// ---------------- stage 2a: fused GEMM -> h1 (cols<1024, SiLU+round) & a1 (SiLU) ----
// A:[M,576] tf32-rounded fp32. W:[576][1280] rounded. 2-stage cp.async, tile 128x128.
__global__ void __launch_bounds__(256, 2)
gemm_fused(const float* __restrict__ A, const float* __restrict__ W,
           const float* __restrict__ bias,
           float* __restrict__ H1, float* __restrict__ A1) {
    extern __shared__ float sm[];
    float* As = sm;
    float* Bs = sm + 2 * A_STAGE;

    const int K = IN_DIM, NcB = NCOMB;
    int t = threadIdx.x;
    int lane = t & 31, warp = t >> 5;
    int wm = warp >> 2, wn = warp & 3;
    int qr = lane >> 2, qc = lane & 3;
    int brow = blockIdx.y * 128;
    int bcol = blockIdx.x * 128;

    float acc[4][4][4];
    #pragma unroll
    for (int i = 0; i < 4; i++)
        #pragma unroll
        for (int j = 0; j < 4; j++)
            #pragma unroll
            for (int k = 0; k < 4; k++) acc[i][j][k] = 0.f;

    int arow = t >> 1, acol = (t & 1) * 16;
    int bkrow = t >> 3, bcol16 = (t & 7) * 16;
    const float* Ag = A + (size_t)(brow + arow) * K + acol;
    const float* Wg = W + (size_t)bkrow * NcB + bcol + bcol16;
    uint32_t AsBase = (uint32_t)__cvta_generic_to_shared(As) + (arow * AST + acol) * 4;
    uint32_t BsBase = (uint32_t)__cvta_generic_to_shared(Bs) + (bkrow * BST + bcol16) * 4;

    int nk = K >> 5;   // 18
    #pragma unroll
    for (int s = 0; s < 2; s++) {
        int k0 = s * 32;
        uint32_t as = AsBase + s * A_STAGE * 4;
        uint32_t bs = BsBase + s * B_STAGE * 4;
        #pragma unroll
        for (int j = 0; j < 4; j++) {
            cp_async16(as + j * 16, Ag + k0 + j * 4);
            cp_async16(bs + j * 16, Wg + (size_t)k0 * NcB + j * 4);
        }
        cp_commit();
    }

    for (int kt = 0; kt < nk; kt++) {
        int buf = kt & 1;
        if (kt + 1 < nk) cp_wait<1>(); else cp_wait<0>();
        __syncthreads();

        const uint32_t* Ab = (const uint32_t*)(As + buf * A_STAGE);
        const uint32_t* Bb = (const uint32_t*)(Bs + buf * B_STAGE);
        #pragma unroll
        for (int ks = 0; ks < 4; ks++) {
            int kc = ks * 8;
            uint32_t a[4][4], b[4][2];
            #pragma unroll
            for (int im = 0; im < 4; im++) {
                int r0 = wm * 64 + im * 16 + qr;
                a[im][0] = Ab[r0 * AST + kc + qc];
                a[im][1] = Ab[(r0 + 8) * AST + kc + qc];
                a[im][2] = Ab[r0 * AST + kc + 4 + qc];
                a[im][3] = Ab[(r0 + 8) * AST + kc + 4 + qc];
            }
            #pragma unroll
            for (int jn = 0; jn < 4; jn++) {
                int c0 = wn * 32 + jn * 8 + qr;
                b[jn][0] = Bb[(kc + qc) * BST + c0];
                b[jn][1] = Bb[(kc + 4 + qc) * BST + c0];
            }
            #pragma unroll
            for (int im = 0; im < 4; im++)
                #pragma unroll
                for (int jn = 0; jn < 4; jn++)
                    mma_tf32(acc[im][jn], a[im], b[jn]);
        }
        __syncthreads();

        if (kt + 2 < nk) {
            int k0 = (kt + 2) * 32;
            uint32_t as = AsBase + buf * A_STAGE * 4;
            uint32_t bs = BsBase + buf * B_STAGE * 4;
            #pragma unroll
            for (int j = 0; j < 4; j++) {
                cp_async16(as + j * 16, Ag + k0 + j * 4);
                cp_async16(bs + j * 16, Wg + (size_t)k0 * NcB + j * 4);
            }
            cp_commit();
        }
    }

    // epilogue: bias + SiLU; route to h1 (round) or a1 based on tile column
    bool is_h1 = (bcol < FEAT_HID);           // tiles never straddle col 1024
    float* Co = is_h1 ? H1 : A1;
    int NcO = is_h1 ? FEAT_HID : ATTN_HID;
    int cb  = is_h1 ? bcol : (bcol - FEAT_HID);

    #pragma unroll
    for (int im = 0; im < 4; im++) {
        #pragma unroll
        for (int jn = 0; jn < 4; jn++) {
            int row  = brow + wm * 64 + im * 16 + qr;
            int colg = bcol + wn * 32 + jn * 8 + 2 * qc;   // global (bias) col
            int colo = cb   + wn * 32 + jn * 8 + 2 * qc;   // output col
            float b0 = bias[colg], b1 = bias[colg + 1];
            float v0 = acc[im][jn][0] + b0;
            float v1 = acc[im][jn][1] + b1;
            float v2 = acc[im][jn][2] + b0;
            float v3 = acc[im][jn][3] + b1;
            v0 = v0 / (1.f + __expf(-v0));
            v1 = v1 / (1.f + __expf(-v1));
            v2 = v2 / (1.f + __expf(-v2));
            v3 = v3 / (1.f + __expf(-v3));
            if (is_h1) {
                v0 = f2tf_f(v0); v1 = f2tf_f(v1);
                v2 = f2tf_f(v2); v3 = f2tf_f(v3);
            }
            float2 r0 = {v0, v1}, r1 = {v2, v3};
            *(float2*)&Co[(size_t)row * NcO + colo] = r0;
            *(float2*)&Co[(size_t)(row + 8) * NcO + colo] = r1;
        }
    }
}

// ---------------- stage 2b: plain GEMM (h1 @ fw2 -> feats, no act) ----------------
__global__ void __launch_bounds__(256, 2)
gemm_plain(const float* __restrict__ A, const float* __restrict__ W,
           const float* __restrict__ bias, float* __restrict__ C,
           int K, int Nc) {
    extern __shared__ float sm[];
    float* As = sm;
    float* Bs = sm + 2 * A_STAGE;

    int t = threadIdx.x;
    int lane = t & 31, warp = t >> 5;
    int wm = warp >> 2, wn = warp & 3;
    int qr = lane >> 2, qc = lane & 3;
    int brow = blockIdx.y * 128;
    int bcol = blockIdx.x * 128;

    float acc[4][4][4];
    #pragma unroll
    for (int i = 0; i < 4; i++)
        #pragma unroll
        for (int j = 0; j < 4; j++)
            #pragma unroll
            for (int k = 0; k < 4; k++) acc[i][j][k] = 0.f;

    int arow = t >> 1, acol = (t & 1) * 16;
    int bkrow = t >> 3, bcol16 = (t & 7) * 16;
    const float* Ag = A + (size_t)(brow + arow) * K + acol;
    const float* Wg = W + (size_t)bkrow * Nc + bcol + bcol16;
    uint32_t AsBase = (uint32_t)__cvta_generic_to_shared(As) + (arow * AST + acol) * 4;
    uint32_t BsBase = (uint32_t)__cvta_generic_to_shared(Bs) + (bkrow * BST + bcol16) * 4;

    int nk = K >> 5;
    #pragma unroll
    for (int s = 0; s < 2; s++) {
        int k0 = s * 32;
        uint32_t as = AsBase + s * A_STAGE * 4;
        uint32_t bs = BsBase + s * B_STAGE * 4;
        #pragma unroll
        for (int j = 0; j < 4; j++) {
            cp_async16(as + j * 16, Ag + k0 + j * 4);
            cp_async16(bs + j * 16, Wg + (size_t)k0 * Nc + j * 4);
        }
        cp_commit();
    }

    for (int kt = 0; kt < nk; kt++) {
        int buf = kt & 1;
        if (kt + 1 < nk) cp_wait<1>(); else cp_wait<0>();
        __syncthreads();

        const uint32_t* Ab = (const uint32_t*)(As + buf * A_STAGE);
        const uint32_t* Bb = (const uint32_t*)(Bs + buf * B_STAGE);
        #pragma unroll
        for (int ks = 0; ks < 4; ks++) {
            int kc = ks * 8;
            uint32_t a[4][4], b[4][2];
            #pragma unroll
            for (int im = 0; im < 4; im++) {
                int r0 = wm * 64 + im * 16 + qr;
                a[im][0] = Ab[r0 * AST + kc + qc];
                a[im][1] = Ab[(r0 + 8) * AST + kc + qc];
                a[im][2] = Ab[r0 * AST + kc + 4 + qc];
                a[im][3] = Ab[(r0 + 8) * AST + kc + 4 + qc];
            }
            #pragma unroll
            for (int jn = 0; jn < 4; jn++) {
                int c0 = wn * 32 + jn * 8 + qr;
                b[jn][0] = Bb[(kc + qc) * BST + c0];
                b[jn][1] = Bb[(kc + 4 + qc) * BST + c0];
            }
            #pragma unroll
            for (int im = 0; im < 4; im++)
                #pragma unroll
                for (int jn = 0; jn < 4; jn++)
                    mma_tf32(acc[im][jn], a[im], b[jn]);
        }
        __syncthreads();

        if (kt + 2 < nk) {
            int k0 = (kt + 2) * 32;
            uint32_t as = AsBase + buf * A_STAGE * 4;
            uint32_t bs = BsBase + buf * B_STAGE * 4;
            #pragma unroll
            for (int j = 0; j < 4; j++) {
                cp_async16(as + j * 16, Ag + k0 + j * 4);
                cp_async16(bs + j * 16, Wg + (size_t)k0 * Nc + j * 4);
            }
            cp_commit();
        }
    }

    #pragma unroll
    for (int im = 0; im < 4; im++) {
        #pragma unroll
        for (int jn = 0; jn < 4; jn++) {
            int row = brow + wm * 64 + im * 16 + qr;
            int col = bcol + wn * 32 + jn * 8 + 2 * qc;
            float b0 = bias[col], b1 = bias[col + 1];
            float2 r0 = {acc[im][jn][0] + b0, acc[im][jn][1] + b1};
            float2 r1 = {acc[im][jn][2] + b0, acc[im][jn][3] + b1};
            *(float2*)&C[(size_t)row * Nc + col] = r0;
            *(float2*)&C[(size_t)(row + 8) * Nc + col] = r1;
        }
    }
}

// ---------------- stage 3: scores = A1 @ aw2 + ab2 ----------------
__global__ void scores_kernel(const float* __restrict__ A1,
                              const float* __restrict__ aw2,
                              const float* __restrict__ ab2) {
    int warp = (blockIdx.x * blockDim.x + threadIdx.x) >> 5;
    int lane = threadIdx.x & 31;
    if (warp >= MROWS) return;
    const float* a = A1 + (size_t)warp * ATTN_HID;
    float acc0 = 0.f, acc1 = 0.f, acc2 = 0.f, acc3 = 0.f;
    #pragma unroll
    for (int c = 0; c < 8; c++) {
        int k = c * 32 + lane;
        float av = a[k];
        float4 w = ((const float4*)aw2)[k];
        acc0 += av * w.x; acc1 += av * w.y; acc2 += av * w.z; acc3 += av * w.w;
    }
    #pragma unroll
    for (int o = 16; o; o >>= 1) {
        acc0 += __shfl_xor_sync(0xFFFFFFFFu, acc0, o);
        acc1 += __shfl_xor_sync(0xFFFFFFFFu, acc1, o);
        acc2 += __shfl_xor_sync(0xFFFFFFFFu, acc2, o);
        acc3 += __shfl_xor_sync(0xFFFFFFFFu, acc3, o);
    }
    if (lane == 0) {
        float4 r;
        r.x = acc0 + ab2[0]; r.y = acc1 + ab2[1];
        r.z = acc2 + ab2[2]; r.w = acc3 + ab2[3];
        ((float4*)g_scores)[warp] = r;
    }
}

// ---------------- stage 4: masked softmax over nodes ----------------
__global__ void softmax_kernel(const int* __restrict__ mask) {
    int b = blockIdx.x;
    int t = threadIdx.x;
    int valid = mask[b * NNODE + t];
    __shared__ float sred[8];
    #pragma unroll
    for (int h = 0; h < NHEADS; h++) {
        float s = valid ? g_scores[((size_t)b * NNODE + t) * NHEADS + h] * 0.0625f
                        : -INFINITY;
        float m = s;
        #pragma unroll
        for (int o = 16; o; o >>= 1) m = fmaxf(m, __shfl_xor_sync(0xFFFFFFFFu, m, o));
        if ((t & 31) == 0) sred[t >> 5] = m;
        __syncthreads();
        m = fmaxf(fmaxf(fmaxf(sred[0], sred[1]), fmaxf(sred[2], sred[3])),
                  fmaxf(fmaxf(sred[4], sred[5]), fmaxf(sred[6], sred[7])));
        __syncthreads();
        float e = expf(s - m);
        float sum = e;
        #pragma unroll
        for (int o = 16; o; o >>= 1) sum += __shfl_xor_sync(0xFFFFFFFFu, sum, o);
        if ((t & 31) == 0) sred[t >> 5] = sum;
        __syncthreads();
        sum = sred[0] + sred[1] + sred[2] + sred[3] +
              sred[4] + sred[5] + sred[6] + sred[7];
        g_w[((size_t)b * NNODE + t) * NHEADS + h] = e / sum;
        __syncthreads();
    }
}

// ---------------- stage 5: residual + mask + attention pooling ----------------
__global__ void finalize_kernel(const float* __restrict__ nodes,
                                const int* __restrict__ mask,
                                float* __restrict__ out) {
    int b = blockIdx.x;
    int c = threadIdx.x;
    int h = c >> 6;
    const float* nb = nodes   + (size_t)b * NNODE * FEAT_OUT;
    const float* fb = g_feats + (size_t)b * NNODE * FEAT_OUT;
    float*       ob = out     + (size_t)b * NNODE * FEAT_OUT;
    float acc = 0.f;
    for (int n = 0; n < NNODE; n++) {
        float f = mask[b * NNODE + n] ? fb[n * FEAT_OUT + c] : 0.f;
        float v = nb[n * FEAT_OUT + c] + f;
        ob[n * FEAT_OUT + c] = v;
        acc += v * g_w[((size_t)b * NNODE + n) * NHEADS + h];
    }
    out[(size_t)MROWS * FEAT_OUT + (size_t)b * FEAT_OUT + c] = acc;
}

// ---------------- launch ----------------
extern "C" void kernel_launch(void* const* d_in, const int* in_sizes, int n_in,
                              void* d_out, int out_size) {
    const float* nodes = (const float*)d_in[0];
    const float* pe    = (const float*)d_in[1];
    const int*   mask  = (const int*)d_in[2];
    const float* globs = (const float*)d_in[3];
    const float* ln_g  = (const float*)d_in[4];
    const float* ln_b  = (const float*)d_in[5];
    const float* fw1   = (const float*)d_in[6];
    const float* fb1   = (const float*)d_in[7];
    const float* fw2   = (const float*)d_in[8];
    const float* fb2   = (const float*)d_in[9];
    const float* aw1   = (const float*)d_in[10];
    const float* ab1   = (const float*)d_in[11];
    const float* aw2   = (const float*)d_in[12];
    const float* ab2   = (const float*)d_in[13];
    float* out = (float*)d_out;

    float *inp, *h1, *a1, *feats, *w1c, *bc, *fw2r;
    cudaGetSymbolAddress((void**)&inp,   g_inp);
    cudaGetSymbolAddress((void**)&h1,    g_h1);
    cudaGetSymbolAddress((void**)&a1,    g_a1);
    cudaGetSymbolAddress((void**)&feats, g_feats);
    cudaGetSymbolAddress((void**)&w1c,   g_w1c);
    cudaGetSymbolAddress((void**)&bc,    g_bc);
    cudaGetSymbolAddress((void**)&fw2r,  g_fw2r);

    cudaFuncSetAttribute(gemm_fused,
                         cudaFuncAttributeMaxDynamicSharedMemorySize, SMEM_BYTES);
    cudaFuncSetAttribute(gemm_plain,
                         cudaFuncAttributeMaxDynamicSharedMemorySize, SMEM_BYTES);

    // launch order chosen so the fused GEMM is the 4th launch (ncu capture slot)
    concat_round_w<<<(IN_DIM * NCOMB + 255) / 256, 256>>>(fw1, aw1, w1c);     // 1
    concat_bias<<<(NCOMB + 255) / 256, 256>>>(fb1, ab1, bc);                  // 2
    prep_kernel<<<MROWS, 128>>>(nodes, pe, globs, ln_g, ln_b);                // 3

    gemm_fused<<<dim3(NCOMB / 128, MROWS / 128), 256, SMEM_BYTES>>>(          // 4 (profiled)
        inp, w1c, bc, h1, a1);

    round_kernel<<<(FEAT_HID * FEAT_OUT + 255) / 256, 256>>>(fw2, fw2r,       // 5
                                                             FEAT_HID * FEAT_OUT);
    gemm_plain<<<dim3(FEAT_OUT / 128, MROWS / 128), 256, SMEM_BYTES>>>(       // 6
        h1, fw2r, fb2, feats, FEAT_HID, FEAT_OUT);

    scores_kernel<<<MROWS / 8, 256>>>(a1, aw2, ab2);                          // 7
    softmax_kernel<<<BATCH, 256>>>(mask);                                     // 8
    finalize_kernel<<<BATCH, 256>>>(nodes, mask, out);                        // 9
}

// round 16
// speedup vs baseline: 1.5385x; 1.5385x over previous
#include <cuda_runtime.h>
#include <math.h>
#include <stdint.h>

// ---------------- problem constants ----------------
#define BATCH    512
#define NNODE    256
#define MROWS    (BATCH*NNODE)   // 131072
#define NODE_D   256
#define FEAT_IN  512
#define GLOB_D   64
#define IN_DIM   576             // FEAT_IN + GLOB_D
#define FEAT_HID 1024
#define ATTN_HID 256
#define FEAT_OUT 256
#define NHEADS   4
#define LN_EPS   1e-5f

// ---------------- scratch (static device globals; no allocation) ----------------
__device__ float g_inp[(size_t)MROWS * IN_DIM];
__device__ float g_h1[(size_t)MROWS * FEAT_HID];
__device__ float g_a1[(size_t)MROWS * ATTN_HID];
__device__ float g_feats[(size_t)MROWS * FEAT_OUT];
__device__ float g_scores[(size_t)MROWS * NHEADS];
__device__ float g_w[(size_t)MROWS * NHEADS];
// pre-transposed + tf32-rounded weights: [N][K]
__device__ float g_fw1t[(size_t)FEAT_HID * IN_DIM];
__device__ float g_aw1t[(size_t)ATTN_HID * IN_DIM];
__device__ float g_fw2t[(size_t)FEAT_OUT * FEAT_HID];

// ---------------- TF32 helpers ----------------
__device__ __forceinline__ uint32_t f2tf(float x) {
    uint32_t r;
    asm("cvt.rna.tf32.f32 %0, %1;" : "=r"(r) : "f"(x));
    return r;
}
__device__ __forceinline__ float f2tf_f(float x) { return __uint_as_float(f2tf(x)); }

__device__ __forceinline__ void mma_tf32(float* c, const uint32_t* a, const uint32_t* b) {
    asm volatile(
        "mma.sync.aligned.m16n8k8.row.col.f32.tf32.tf32.f32 "
        "{%0,%1,%2,%3}, {%4,%5,%6,%7}, {%8,%9}, {%0,%1,%2,%3};"
        : "+f"(c[0]), "+f"(c[1]), "+f"(c[2]), "+f"(c[3])
        : "r"(a[0]), "r"(a[1]), "r"(a[2]), "r"(a[3]), "r"(b[0]), "r"(b[1]));
}

// ---------------- ldmatrix helpers (b16 form works for b32 data: bits only) ----------
__device__ __forceinline__ void ldsm_x4(uint32_t& r0, uint32_t& r1, uint32_t& r2,
                                        uint32_t& r3, uint32_t addr) {
    asm volatile("ldmatrix.sync.aligned.m8n8.x4.shared.b16 {%0,%1,%2,%3}, [%4];"
                 : "=r"(r0), "=r"(r1), "=r"(r2), "=r"(r3) : "r"(addr));
}
__device__ __forceinline__ void ldsm_x2(uint32_t& r0, uint32_t& r1, uint32_t addr) {
    asm volatile("ldmatrix.sync.aligned.m8n8.x2.shared.b16 {%0,%1}, [%2];"
                 : "=r"(r0), "=r"(r1) : "r"(addr));
}

// ---------------- cp.async helpers ----------------
__device__ __forceinline__ void cp_async16(uint32_t saddr, const void* g) {
    asm volatile("cp.async.cg.shared.global [%0], [%1], 16;" :: "r"(saddr), "l"(g));
}
__device__ __forceinline__ void cp_commit() {
    asm volatile("cp.async.commit_group;");
}
template <int N>
__device__ __forceinline__ void cp_wait() {
    asm volatile("cp.async.wait_group %0;" :: "n"(N));
}

// ---------------- stage 0: transpose + tf32-round weights W[K][N] -> Wt[N][K] -------
__global__ void transpose_round(const float* __restrict__ W, float* __restrict__ Wt,
                                int Kd, int Nd) {
    __shared__ float t[32][33];
    int bx = blockIdx.x * 32, by = blockIdx.y * 32;
    int x = threadIdx.x, y = threadIdx.y;
    #pragma unroll
    for (int j = 0; j < 32; j += 8)
        t[y + j][x] = W[(size_t)(by + y + j) * Nd + bx + x];
    __syncthreads();
    #pragma unroll
    for (int j = 0; j < 32; j += 8)
        Wt[(size_t)(bx + y + j) * Kd + by + x] = f2tf_f(t[x][y + j]);
}

// ---------------- stage 1: LayerNorm(concat) + ctx concat (tf32-rounded) ----------------
__global__ void prep_kernel(const float* __restrict__ nodes,
                            const float* __restrict__ pe,
                            const float* __restrict__ globs,
                            const float* __restrict__ ln_g,
                            const float* __restrict__ ln_b) {
    int row = blockIdx.x;
    int t = threadIdx.x;        // 0..127
    int b = row >> 8;

    float4 v;
    if (t < 64) v = ((const float4*)(nodes + (size_t)row * NODE_D))[t];
    else        v = ((const float4*)(pe    + (size_t)row * NODE_D))[t - 64];

    float s  = v.x + v.y + v.z + v.w;
    float ss = v.x * v.x + v.y * v.y + v.z * v.z + v.w * v.w;
    #pragma unroll
    for (int o = 16; o; o >>= 1) {
        s  += __shfl_xor_sync(0xFFFFFFFFu, s, o);
        ss += __shfl_xor_sync(0xFFFFFFFFu, ss, o);
    }
    __shared__ float sh_s[4], sh_ss[4];
    if ((t & 31) == 0) { sh_s[t >> 5] = s; sh_ss[t >> 5] = ss; }
    __syncthreads();
    float mean = (sh_s[0] + sh_s[1] + sh_s[2] + sh_s[3]) * (1.f / 512.f);
    float m2   = (sh_ss[0] + sh_ss[1] + sh_ss[2] + sh_ss[3]) * (1.f / 512.f);
    float rstd = rsqrtf(m2 - mean * mean + LN_EPS);

    float4 g  = ((const float4*)ln_g)[t];
    float4 bt = ((const float4*)ln_b)[t];
    float4 o;
    o.x = f2tf_f((v.x - mean) * rstd * g.x + bt.x);
    o.y = f2tf_f((v.y - mean) * rstd * g.y + bt.y);
    o.z = f2tf_f((v.z - mean) * rstd * g.z + bt.z);
    o.w = f2tf_f((v.w - mean) * rstd * g.w + bt.w);
    ((float4*)(g_inp + (size_t)row * IN_DIM))[t] = o;
    if (t < 16) {
        float4 c = ((const float4*)(globs + (size_t)b * GLOB_D))[t];
        c.x = f2tf_f(c.x); c.y = f2tf_f(c.y); c.z = f2tf_f(c.z); c.w = f2tf_f(c.w);
        ((float4*)(g_inp + (size_t)row * IN_DIM + FEAT_IN))[t] = c;
    }
}

// ---------------- stage 2: TF32 GEMM, ldmatrix frags, 2-stage cp.async ----------------
// C[M,Nc] = act(A[M,K] @ Wt[Nc,K]^T + bias). Tile 128x128, BK=32.
// A row-major [M][K]; Wt pre-transposed [Nc][K]. Both smem tiles: 128 rows x 32 f32,
// row stride 36 floats (144B) -> conflict-free ldmatrix phases.
#define TST 36   // smem row stride (floats) for both A and B tiles
#define T_STAGE (128 * TST)          // 4608 floats per tile
#define STAGE_F (2 * T_STAGE)        // A + B per stage
#define SMEM_BYTES (2 * STAGE_F * 4) // 2 stages = 73728 B

template <bool SILU, bool ROUND_OUT>
__global__ void __launch_bounds__(256, 2)
gemm_ldsm(const float* __restrict__ A, const float* __restrict__ Wt,
          const float* __restrict__ bias, float* __restrict__ C,
          int K, int Nc) {
    extern __shared__ float sm[];

    int t = threadIdx.x;
    int lane = t & 31, warp = t >> 5;
    int wm = warp >> 2, wn = warp & 3;           // 2 x 4 warp grid
    int qr = lane >> 2, qc = lane & 3;
    int brow = blockIdx.y * 128;
    int bcol = blockIdx.x * 128;

    float acc[4][4][4];
    #pragma unroll
    for (int i = 0; i < 4; i++)
        #pragma unroll
        for (int j = 0; j < 4; j++)
            #pragma unroll
            for (int k = 0; k < 4; k++) acc[i][j][k] = 0.f;

    // cp.async mapping: thread -> row t>>1 (0..127), 16 floats at (t&1)*16.
    // Identical shape for A (M-rows) and B (N-rows of Wt).
    int srow = t >> 1, scol = (t & 1) * 16;
    const float* Ag = A  + (size_t)(brow + srow) * K + scol;
    const float* Wg = Wt + (size_t)(bcol + srow) * K + scol;
    uint32_t smBase = (uint32_t)__cvta_generic_to_shared(sm);
    uint32_t AsW = smBase + (srow * TST + scol) * 4;
    uint32_t BsW = smBase + (T_STAGE + srow * TST + scol) * 4;

    // ldmatrix per-lane offsets (bytes)
    uint32_t a_off = ((lane & 15) * TST + (lane >> 4) * 4) * 4;
    uint32_t b_off = ((lane & 7) * TST + ((lane >> 3) & 1) * 4) * 4;

    int nk = K >> 5;

    #pragma unroll
    for (int s = 0; s < 2; s++) {
        int k0 = s * 32;
        uint32_t as = AsW + s * STAGE_F * 4;
        uint32_t bs = BsW + s * STAGE_F * 4;
        #pragma unroll
        for (int j = 0; j < 4; j++) {
            cp_async16(as + j * 16, Ag + k0 + j * 4);
            cp_async16(bs + j * 16, Wg + k0 + j * 4);
        }
        cp_commit();
    }

    for (int kt = 0; kt < nk; kt++) {
        int buf = kt & 1;
        if (kt + 1 < nk) cp_wait<1>(); else cp_wait<0>();
        __syncthreads();

        uint32_t sA = smBase + buf * STAGE_F * 4;
        uint32_t sB = sA + T_STAGE * 4;
        #pragma unroll
        for (int ks = 0; ks < 4; ks++) {
            int kc = ks * 8;
            uint32_t a[4][4], b[4][2];
            #pragma unroll
            for (int im = 0; im < 4; im++) {
                uint32_t addr = sA + ((wm * 64 + im * 16) * TST + kc) * 4 + a_off;
                ldsm_x4(a[im][0], a[im][1], a[im][2], a[im][3], addr);
            }
            #pragma unroll
            for (int jn = 0; jn < 4; jn++) {
                uint32_t addr = sB + ((wn * 32 + jn * 8) * TST + kc) * 4 + b_off;
                ldsm_x2(b[jn][0], b[jn][1], addr);
            }
            #pragma unroll
            for (int im = 0; im < 4; im++)
                #pragma unroll
                for (int jn = 0; jn < 4; jn++)
                    mma_tf32(acc[im][jn], a[im], b[jn]);
        }
        __syncthreads();

        if (kt + 2 < nk) {
            int k0 = (kt + 2) * 32;
            uint32_t as = AsW + buf * STAGE_F * 4;
            uint32_t bs = BsW + buf * STAGE_F * 4;
            #pragma unroll
            for (int j = 0; j < 4; j++) {
                cp_async16(as + j * 16, Ag + k0 + j * 4);
                cp_async16(bs + j * 16, Wg + k0 + j * 4);
            }
            cp_commit();
        }
    }

    // epilogue: bias + optional SiLU (+ optional tf32 re-round)
    #pragma unroll
    for (int im = 0; im < 4; im++) {
        #pragma unroll
        for (int jn = 0; jn < 4; jn++) {
            int row = brow + wm * 64 + im * 16 + qr;
            int col = bcol + wn * 32 + jn * 8 + 2 * qc;
            float b0 = __ldg(&bias[col]), b1 = __ldg(&bias[col + 1]);
            float v0 = acc[im][jn][0] + b0;
            float v1 = acc[im][jn][1] + b1;
            float v2 = acc[im][jn][2] + b0;
            float v3 = acc[im][jn][3] + b1;
            if (SILU) {
                v0 = v0 / (1.f + __expf(-v0));
                v1 = v1 / (1.f + __expf(-v1));
                v2 = v2 / (1.f + __expf(-v2));
                v3 = v3 / (1.f + __expf(-v3));
            }
            if (ROUND_OUT) {
                v0 = f2tf_f(v0); v1 = f2tf_f(v1);
                v2 = f2tf_f(v2); v3 = f2tf_f(v3);
            }
            float2 r0 = {v0, v1}, r1 = {v2, v3};
            *(float2*)&C[(size_t)row * Nc + col] = r0;
            *(float2*)&C[(size_t)(row + 8) * Nc + col] = r1;
        }
    }
}

// ---------------- stage 3: scores = A1 @ aw2 + ab2 ----------------
__global__ void scores_kernel(const float* __restrict__ A1,
                              const float* __restrict__ aw2,
                              const float* __restrict__ ab2) {
    int warp = (blockIdx.x * blockDim.x + threadIdx.x) >> 5;
    int lane = threadIdx.x & 31;
    if (warp >= MROWS) return;
    const float* a = A1 + (size_t)warp * ATTN_HID;
    float acc0 = 0.f, acc1 = 0.f, acc2 = 0.f, acc3 = 0.f;
    #pragma unroll
    for (int c = 0; c < 8; c++) {
        int k = c * 32 + lane;
        float av = a[k];
        float4 w = ((const float4*)aw2)[k];
        acc0 += av * w.x; acc1 += av * w.y; acc2 += av * w.z; acc3 += av * w.w;
    }
    #pragma unroll
    for (int o = 16; o; o >>= 1) {
        acc0 += __shfl_xor_sync(0xFFFFFFFFu, acc0, o);
        acc1 += __shfl_xor_sync(0xFFFFFFFFu, acc1, o);
        acc2 += __shfl_xor_sync(0xFFFFFFFFu, acc2, o);
        acc3 += __shfl_xor_sync(0xFFFFFFFFu, acc3, o);
    }
    if (lane == 0) {
        float4 r;
        r.x = acc0 + ab2[0]; r.y = acc1 + ab2[1];
        r.z = acc2 + ab2[2]; r.w = acc3 + ab2[3];
        ((float4*)g_scores)[warp] = r;
    }
}

// ---------------- stage 4: masked softmax over nodes ----------------
__global__ void softmax_kernel(const int* __restrict__ mask) {
    int b = blockIdx.x;
    int t = threadIdx.x;
    int valid = mask[b * NNODE + t];
    __shared__ float sred[8];
    #pragma unroll
    for (int h = 0; h < NHEADS; h++) {
        float s = valid ? g_scores[((size_t)b * NNODE + t) * NHEADS + h] * 0.0625f
                        : -INFINITY;
        float m = s;
        #pragma unroll
        for (int o = 16; o; o >>= 1) m = fmaxf(m, __shfl_xor_sync(0xFFFFFFFFu, m, o));
        if ((t & 31) == 0) sred[t >> 5] = m;
        __syncthreads();
        m = fmaxf(fmaxf(fmaxf(sred[0], sred[1]), fmaxf(sred[2], sred[3])),
                  fmaxf(fmaxf(sred[4], sred[5]), fmaxf(sred[6], sred[7])));
        __syncthreads();
        float e = expf(s - m);
        float sum = e;
        #pragma unroll
        for (int o = 16; o; o >>= 1) sum += __shfl_xor_sync(0xFFFFFFFFu, sum, o);
        if ((t & 31) == 0) sred[t >> 5] = sum;
        __syncthreads();
        sum = sred[0] + sred[1] + sred[2] + sred[3] +
              sred[4] + sred[5] + sred[6] + sred[7];
        g_w[((size_t)b * NNODE + t) * NHEADS + h] = e / sum;
        __syncthreads();
    }
}

// ---------------- stage 5: residual + mask + attention pooling ----------------
__global__ void finalize_kernel(const float* __restrict__ nodes,
                                const int* __restrict__ mask,
                                float* __restrict__ out) {
    int b = blockIdx.x;
    int c = threadIdx.x;
    int h = c >> 6;
    const float* nb = nodes   + (size_t)b * NNODE * FEAT_OUT;
    const float* fb = g_feats + (size_t)b * NNODE * FEAT_OUT;
    float*       ob = out     + (size_t)b * NNODE * FEAT_OUT;
    float acc = 0.f;
    for (int n = 0; n < NNODE; n++) {
        float f = mask[b * NNODE + n] ? fb[n * FEAT_OUT + c] : 0.f;
        float v = nb[n * FEAT_OUT + c] + f;
        ob[n * FEAT_OUT + c] = v;
        acc += v * g_w[((size_t)b * NNODE + n) * NHEADS + h];
    }
    out[(size_t)MROWS * FEAT_OUT + (size_t)b * FEAT_OUT + c] = acc;
}

// ---------------- launch ----------------
extern "C" void kernel_launch(void* const* d_in, const int* in_sizes, int n_in,
                              void* d_out, int out_size) {
    const float* nodes = (const float*)d_in[0];
    const float* pe    = (const float*)d_in[1];
    const int*   mask  = (const int*)d_in[2];
    const float* globs = (const float*)d_in[3];
    const float* ln_g  = (const float*)d_in[4];
    const float* ln_b  = (const float*)d_in[5];
    const float* fw1   = (const float*)d_in[6];
    const float* fb1   = (const float*)d_in[7];
    const float* fw2   = (const float*)d_in[8];
    const float* fb2   = (const float*)d_in[9];
    const float* aw1   = (const float*)d_in[10];
    const float* ab1   = (const float*)d_in[11];
    const float* aw2   = (const float*)d_in[12];
    const float* ab2   = (const float*)d_in[13];
    float* out = (float*)d_out;

    float *inp, *h1, *a1, *feats, *fw1t, *aw1t, *fw2t;
    cudaGetSymbolAddress((void**)&inp,   g_inp);
    cudaGetSymbolAddress((void**)&h1,    g_h1);
    cudaGetSymbolAddress((void**)&a1,    g_a1);
    cudaGetSymbolAddress((void**)&feats, g_feats);
    cudaGetSymbolAddress((void**)&fw1t,  g_fw1t);
    cudaGetSymbolAddress((void**)&aw1t,  g_aw1t);
    cudaGetSymbolAddress((void**)&fw2t,  g_fw2t);

    cudaFuncSetAttribute(gemm_ldsm<true, true>,
                         cudaFuncAttributeMaxDynamicSharedMemorySize, SMEM_BYTES);
    cudaFuncSetAttribute(gemm_ldsm<true, false>,
                         cudaFuncAttributeMaxDynamicSharedMemorySize, SMEM_BYTES);
    cudaFuncSetAttribute(gemm_ldsm<false, false>,
                         cudaFuncAttributeMaxDynamicSharedMemorySize, SMEM_BYTES);

    // ordered so the big GEMM is the 4th launch (ncu capture slot)
    prep_kernel<<<MROWS, 128>>>(nodes, pe, globs, ln_g, ln_b);                       // 1
    transpose_round<<<dim3(FEAT_HID / 32, IN_DIM / 32), dim3(32, 8)>>>(              // 2
        fw1, fw1t, IN_DIM, FEAT_HID);
    transpose_round<<<dim3(ATTN_HID / 32, IN_DIM / 32), dim3(32, 8)>>>(              // 3
        aw1, aw1t, IN_DIM, ATTN_HID);

    gemm_ldsm<true, true><<<dim3(FEAT_HID / 128, MROWS / 128), 256, SMEM_BYTES>>>(   // 4 (profiled)
        inp, fw1t, fb1, h1, IN_DIM, FEAT_HID);
    gemm_ldsm<true, false><<<dim3(ATTN_HID / 128, MROWS / 128), 256, SMEM_BYTES>>>(  // 5
        inp, aw1t, ab1, a1, IN_DIM, ATTN_HID);

    transpose_round<<<dim3(FEAT_OUT / 32, FEAT_HID / 32), dim3(32, 8)>>>(            // 6
        fw2, fw2t, FEAT_HID, FEAT_OUT);
    gemm_ldsm<false, false><<<dim3(FEAT_OUT / 128, MROWS / 128), 256, SMEM_BYTES>>>( // 7
        h1, fw2t, fb2, feats, FEAT_HID, FEAT_OUT);

    scores_kernel<<<MROWS / 8, 256>>>(a1, aw2, ab2);                                 // 8
    softmax_kernel<<<BATCH, 256>>>(mask);                                            // 9
    finalize_kernel<<<BATCH, 256>>>(nodes, mask, out);                               // 10
}

// round 17
// speedup vs baseline: 1.5508x; 1.0080x over previous
#include <cuda_runtime.h>
#include <math.h>
#include <stdint.h>

// ---------------- problem constants ----------------
#define BATCH    512
#define NNODE    256
#define MROWS    (BATCH*NNODE)   // 131072
#define NODE_D   256
#define FEAT_IN  512
#define GLOB_D   64
#define IN_DIM   576             // FEAT_IN + GLOB_D
#define FEAT_HID 1024
#define ATTN_HID 256
#define FEAT_OUT 256
#define NHEADS   4
#define LN_EPS   1e-5f

// ---------------- scratch (static device globals; no allocation) ----------------
__device__ float g_inp[(size_t)MROWS * IN_DIM];
__device__ float g_h1[(size_t)MROWS * FEAT_HID];
__device__ float g_sp[(size_t)MROWS * 16];          // partial scores [row][4 slots][4 heads]
__device__ float g_w[(size_t)MROWS * NHEADS];
__device__ float g_fw1r[(size_t)IN_DIM * FEAT_HID];
__device__ float g_aw1r[(size_t)IN_DIM * ATTN_HID];
__device__ float g_fw2r[(size_t)FEAT_HID * FEAT_OUT];

// ---------------- TF32 helpers ----------------
__device__ __forceinline__ uint32_t f2tf(float x) {
    uint32_t r;
    asm("cvt.rna.tf32.f32 %0, %1;" : "=r"(r) : "f"(x));
    return r;
}
__device__ __forceinline__ float f2tf_f(float x) { return __uint_as_float(f2tf(x)); }

__device__ __forceinline__ void mma_tf32(float* c, const uint32_t* a, const uint32_t* b) {
    asm volatile(
        "mma.sync.aligned.m16n8k8.row.col.f32.tf32.tf32.f32 "
        "{%0,%1,%2,%3}, {%4,%5,%6,%7}, {%8,%9}, {%0,%1,%2,%3};"
        : "+f"(c[0]), "+f"(c[1]), "+f"(c[2]), "+f"(c[3])
        : "r"(a[0]), "r"(a[1]), "r"(a[2]), "r"(a[3]), "r"(b[0]), "r"(b[1]));
}

// ---------------- cp.async helpers ----------------
__device__ __forceinline__ void cp_async16(uint32_t saddr, const void* g) {
    asm volatile("cp.async.cg.shared.global [%0], [%1], 16;" :: "r"(saddr), "l"(g));
}
__device__ __forceinline__ void cp_commit() {
    asm volatile("cp.async.commit_group;");
}
template <int N>
__device__ __forceinline__ void cp_wait() {
    asm volatile("cp.async.wait_group %0;" :: "n"(N));
}

// ---------------- stage 0: round weights to tf32 (RNA) ----------------
__global__ void round_kernel(const float* __restrict__ in, float* __restrict__ out, int n) {
    int i = blockIdx.x * blockDim.x + threadIdx.x;
    if (i < n) out[i] = f2tf_f(in[i]);
}

// ---------------- stage 1: LayerNorm(concat) + ctx concat (tf32-rounded) ----------------
__global__ void prep_kernel(const float* __restrict__ nodes,
                            const float* __restrict__ pe,
                            const float* __restrict__ globs,
                            const float* __restrict__ ln_g,
                            const float* __restrict__ ln_b) {
    int row = blockIdx.x;
    int t = threadIdx.x;        // 0..127
    int b = row >> 8;

    float4 v;
    if (t < 64) v = ((const float4*)(nodes + (size_t)row * NODE_D))[t];
    else        v = ((const float4*)(pe    + (size_t)row * NODE_D))[t - 64];

    float s  = v.x + v.y + v.z + v.w;
    float ss = v.x * v.x + v.y * v.y + v.z * v.z + v.w * v.w;
    #pragma unroll
    for (int o = 16; o; o >>= 1) {
        s  += __shfl_xor_sync(0xFFFFFFFFu, s, o);
        ss += __shfl_xor_sync(0xFFFFFFFFu, ss, o);
    }
    __shared__ float sh_s[4], sh_ss[4];
    if ((t & 31) == 0) { sh_s[t >> 5] = s; sh_ss[t >> 5] = ss; }
    __syncthreads();
    float mean = (sh_s[0] + sh_s[1] + sh_s[2] + sh_s[3]) * (1.f / 512.f);
    float m2   = (sh_ss[0] + sh_ss[1] + sh_ss[2] + sh_ss[3]) * (1.f / 512.f);
    float rstd = rsqrtf(m2 - mean * mean + LN_EPS);

    float4 g  = ((const float4*)ln_g)[t];
    float4 bt = ((const float4*)ln_b)[t];
    float4 o;
    o.x = f2tf_f((v.x - mean) * rstd * g.x + bt.x);
    o.y = f2tf_f((v.y - mean) * rstd * g.y + bt.y);
    o.z = f2tf_f((v.z - mean) * rstd * g.z + bt.z);
    o.w = f2tf_f((v.w - mean) * rstd * g.w + bt.w);
    ((float4*)(g_inp + (size_t)row * IN_DIM))[t] = o;
    if (t < 16) {
        float4 c = ((const float4*)(globs + (size_t)b * GLOB_D))[t];
        c.x = f2tf_f(c.x); c.y = f2tf_f(c.y); c.z = f2tf_f(c.z); c.w = f2tf_f(c.w);
        ((float4*)(g_inp + (size_t)row * IN_DIM + FEAT_IN))[t] = c;
    }
}

// ---------------- R7 GEMM mainloop (shared by all three GEMMs) ----------------
#define AST 36   // As row stride (floats)
#define BST 136  // Bs row stride (floats)
#define A_STAGE (128 * AST)
#define B_STAGE (32 * BST)
#define SMEM_FLOATS (2 * (A_STAGE + B_STAGE))
#define SMEM_BYTES (SMEM_FLOATS * 4)

__device__ __forceinline__ void gemm_mainloop(
    const float* __restrict__ A, const float* __restrict__ W,
    int K, int Nc, int brow, int bcol, float* sm,
    float acc[4][4][4], int t, int wm, int wn) {

    float* As = sm;
    float* Bs = sm + 2 * A_STAGE;

    #pragma unroll
    for (int i = 0; i < 4; i++)
        #pragma unroll
        for (int j = 0; j < 4; j++)
            #pragma unroll
            for (int k = 0; k < 4; k++) acc[i][j][k] = 0.f;

    int arow = t >> 1, acol = (t & 1) * 16;
    int bkrow = t >> 3, bcol16 = (t & 7) * 16;
    const float* Ag = A + (size_t)(brow + arow) * K + acol;
    const float* Wg = W + (size_t)bkrow * Nc + bcol + bcol16;
    uint32_t AsBase = (uint32_t)__cvta_generic_to_shared(As) + (arow * AST + acol) * 4;
    uint32_t BsBase = (uint32_t)__cvta_generic_to_shared(Bs) + (bkrow * BST + bcol16) * 4;

    int lane = t & 31;
    int qr = lane >> 2, qc = lane & 3;
    int nk = K >> 5;

    #pragma unroll
    for (int s = 0; s < 2; s++) {
        int k0 = s * 32;
        uint32_t as = AsBase + s * A_STAGE * 4;
        uint32_t bs = BsBase + s * B_STAGE * 4;
        #pragma unroll
        for (int j = 0; j < 4; j++) {
            cp_async16(as + j * 16, Ag + k0 + j * 4);
            cp_async16(bs + j * 16, Wg + (size_t)k0 * Nc + j * 4);
        }
        cp_commit();
    }

    for (int kt = 0; kt < nk; kt++) {
        int buf = kt & 1;
        if (kt + 1 < nk) cp_wait<1>(); else cp_wait<0>();
        __syncthreads();

        const uint32_t* Ab = (const uint32_t*)(As + buf * A_STAGE);
        const uint32_t* Bb = (const uint32_t*)(Bs + buf * B_STAGE);
        #pragma unroll
        for (int ks = 0; ks < 4; ks++) {
            int kc = ks * 8;
            uint32_t a[4][4], b[4][2];
            #pragma unroll
            for (int im = 0; im < 4; im++) {
                int r0 = wm * 64 + im * 16 + qr;
                a[im][0] = Ab[r0 * AST + kc + qc];
                a[im][1] = Ab[(r0 + 8) * AST + kc + qc];
                a[im][2] = Ab[r0 * AST + kc + 4 + qc];
                a[im][3] = Ab[(r0 + 8) * AST + kc + 4 + qc];
            }
            #pragma unroll
            for (int jn = 0; jn < 4; jn++) {
                int c0 = wn * 32 + jn * 8 + qr;
                b[jn][0] = Bb[(kc + qc) * BST + c0];
                b[jn][1] = Bb[(kc + 4 + qc) * BST + c0];
            }
            #pragma unroll
            for (int im = 0; im < 4; im++)
                #pragma unroll
                for (int jn = 0; jn < 4; jn++)
                    mma_tf32(acc[im][jn], a[im], b[jn]);
        }
        __syncthreads();

        if (kt + 2 < nk) {
            int k0 = (kt + 2) * 32;
            uint32_t as = AsBase + buf * A_STAGE * 4;
            uint32_t bs = BsBase + buf * B_STAGE * 4;
            #pragma unroll
            for (int j = 0; j < 4; j++) {
                cp_async16(as + j * 16, Ag + k0 + j * 4);
                cp_async16(bs + j * 16, Wg + (size_t)k0 * Nc + j * 4);
            }
            cp_commit();
        }
    }
}

// ---------------- GEMM-1: inp @ fw1 -> h1 (SiLU + tf32 round) ----------------
__global__ void __launch_bounds__(256, 2)
gemm1_kernel(const float* __restrict__ A, const float* __restrict__ W,
             const float* __restrict__ bias, float* __restrict__ C) {
    extern __shared__ float sm[];
    int t = threadIdx.x;
    int lane = t & 31, warp = t >> 5;
    int wm = warp >> 2, wn = warp & 3;
    int qr = lane >> 2, qc = lane & 3;
    int brow = blockIdx.y * 128, bcol = blockIdx.x * 128;

    float acc[4][4][4];
    gemm_mainloop(A, W, IN_DIM, FEAT_HID, brow, bcol, sm, acc, t, wm, wn);

    #pragma unroll
    for (int im = 0; im < 4; im++) {
        #pragma unroll
        for (int jn = 0; jn < 4; jn++) {
            int row = brow + wm * 64 + im * 16 + qr;
            int col = bcol + wn * 32 + jn * 8 + 2 * qc;
            float b0 = bias[col], b1 = bias[col + 1];
            float v0 = acc[im][jn][0] + b0;
            float v1 = acc[im][jn][1] + b1;
            float v2 = acc[im][jn][2] + b0;
            float v3 = acc[im][jn][3] + b1;
            v0 = v0 / (1.f + __expf(-v0));
            v1 = v1 / (1.f + __expf(-v1));
            v2 = v2 / (1.f + __expf(-v2));
            v3 = v3 / (1.f + __expf(-v3));
            v0 = f2tf_f(v0); v1 = f2tf_f(v1);
            v2 = f2tf_f(v2); v3 = f2tf_f(v3);
            float2 r0 = {v0, v1}, r1 = {v2, v3};
            *(float2*)&C[(size_t)row * FEAT_HID + col] = r0;
            *(float2*)&C[(size_t)(row + 8) * FEAT_HID + col] = r1;
        }
    }
}

// ---------------- GEMM-2 fused: inp @ aw1 -> SiLU -> partial scores (a1 never stored) --
// grid (2, 1024); each CTA covers 128 cols of a1. Stages a1 tile in smem, then ordered
// 64-col dot with aw2 -> g_sp[row][slot=bx*2+half][head], deterministic.
#define DST 132
__global__ void __launch_bounds__(256, 2)
gemm2_kernel(const float* __restrict__ A, const float* __restrict__ W,
             const float* __restrict__ bias, const float* __restrict__ aw2) {
    extern __shared__ float sm[];
    int t = threadIdx.x;
    int lane = t & 31, warp = t >> 5;
    int wm = warp >> 2, wn = warp & 3;
    int qr = lane >> 2, qc = lane & 3;
    int brow = blockIdx.y * 128, bcol = blockIdx.x * 128;

    float acc[4][4][4];
    gemm_mainloop(A, W, IN_DIM, ATTN_HID, brow, bcol, sm, acc, t, wm, wn);

    // stage SiLU(a1) tile into smem (mainloop left all warps past its last sync)
    float* Ds = sm;   // 128 x DST floats = 67.6KB <= 73.7KB
    #pragma unroll
    for (int im = 0; im < 4; im++) {
        #pragma unroll
        for (int jn = 0; jn < 4; jn++) {
            int rl = wm * 64 + im * 16 + qr;
            int lc = wn * 32 + jn * 8 + 2 * qc;
            float b0 = bias[bcol + lc], b1 = bias[bcol + lc + 1];
            float v0 = acc[im][jn][0] + b0;
            float v1 = acc[im][jn][1] + b1;
            float v2 = acc[im][jn][2] + b0;
            float v3 = acc[im][jn][3] + b1;
            v0 = v0 / (1.f + __expf(-v0));
            v1 = v1 / (1.f + __expf(-v1));
            v2 = v2 / (1.f + __expf(-v2));
            v3 = v3 / (1.f + __expf(-v3));
            Ds[rl * DST + lc]           = v0;
            Ds[rl * DST + lc + 1]       = v1;
            Ds[(rl + 8) * DST + lc]     = v2;
            Ds[(rl + 8) * DST + lc + 1] = v3;
        }
    }
    __syncthreads();

    // partial scores: thread t -> row t>>1, half t&1 (64 cols), fixed order
    int rl = t >> 1, half = t & 1;
    int cbase = half * 64;
    float s0 = 0.f, s1 = 0.f, s2 = 0.f, s3 = 0.f;
    #pragma unroll 8
    for (int c = 0; c < 64; c++) {
        float av = Ds[rl * DST + cbase + c];
        float4 w = ((const float4*)aw2)[bcol + cbase + c];
        s0 += av * w.x; s1 += av * w.y; s2 += av * w.z; s3 += av * w.w;
    }
    int rg = brow + rl;
    int slot = blockIdx.x * 2 + half;
    float4 r = {s0, s1, s2, s3};
    ((float4*)g_sp)[(size_t)rg * 4 + slot] = r;
}

// ---------------- GEMM-3 fused: h1 @ fw2 + bias, mask, +nodes -> out (new_nodes) -----
__global__ void __launch_bounds__(256, 2)
gemm3_kernel(const float* __restrict__ A, const float* __restrict__ W,
             const float* __restrict__ bias, const float* __restrict__ nodes,
             const int* __restrict__ mask, float* __restrict__ out) {
    extern __shared__ float sm[];
    int t = threadIdx.x;
    int lane = t & 31, warp = t >> 5;
    int wm = warp >> 2, wn = warp & 3;
    int qr = lane >> 2, qc = lane & 3;
    int brow = blockIdx.y * 128, bcol = blockIdx.x * 128;

    float acc[4][4][4];
    gemm_mainloop(A, W, FEAT_HID, FEAT_OUT, brow, bcol, sm, acc, t, wm, wn);

    #pragma unroll
    for (int im = 0; im < 4; im++) {
        #pragma unroll
        for (int jn = 0; jn < 4; jn++) {
            int row = brow + wm * 64 + im * 16 + qr;
            int col = bcol + wn * 32 + jn * 8 + 2 * qc;
            float b0 = bias[col], b1 = bias[col + 1];
            int m0 = mask[row], m1 = mask[row + 8];
            float2 n0 = *(const float2*)&nodes[(size_t)row * FEAT_OUT + col];
            float2 n1 = *(const float2*)&nodes[(size_t)(row + 8) * FEAT_OUT + col];
            float v0 = m0 ? (acc[im][jn][0] + b0) : 0.f;
            float v1 = m0 ? (acc[im][jn][1] + b1) : 0.f;
            float v2 = m1 ? (acc[im][jn][2] + b0) : 0.f;
            float v3 = m1 ? (acc[im][jn][3] + b1) : 0.f;
            float2 r0 = {v0 + n0.x, v1 + n0.y};
            float2 r1 = {v2 + n1.x, v3 + n1.y};
            *(float2*)&out[(size_t)row * FEAT_OUT + col] = r0;
            *(float2*)&out[(size_t)(row + 8) * FEAT_OUT + col] = r1;
        }
    }
}

// ---------------- stage 4: combine partial scores + masked softmax ----------------
__global__ void softmax_kernel(const int* __restrict__ mask,
                               const float* __restrict__ ab2) {
    int b = blockIdx.x;
    int t = threadIdx.x;      // node index
    int valid = mask[b * NNODE + t];
    size_t rg = (size_t)b * NNODE + t;

    float sc[NHEADS];
    {
        float4 p0 = ((const float4*)g_sp)[rg * 4 + 0];
        float4 p1 = ((const float4*)g_sp)[rg * 4 + 1];
        float4 p2 = ((const float4*)g_sp)[rg * 4 + 2];
        float4 p3 = ((const float4*)g_sp)[rg * 4 + 3];
        sc[0] = ((p0.x + p1.x) + (p2.x + p3.x)) + ab2[0];
        sc[1] = ((p0.y + p1.y) + (p2.y + p3.y)) + ab2[1];
        sc[2] = ((p0.z + p1.z) + (p2.z + p3.z)) + ab2[2];
        sc[3] = ((p0.w + p1.w) + (p2.w + p3.w)) + ab2[3];
    }

    __shared__ float sred[8];
    #pragma unroll
    for (int h = 0; h < NHEADS; h++) {
        float s = valid ? sc[h] * 0.0625f : -INFINITY;
        float m = s;
        #pragma unroll
        for (int o = 16; o; o >>= 1) m = fmaxf(m, __shfl_xor_sync(0xFFFFFFFFu, m, o));
        if ((t & 31) == 0) sred[t >> 5] = m;
        __syncthreads();
        m = fmaxf(fmaxf(fmaxf(sred[0], sred[1]), fmaxf(sred[2], sred[3])),
                  fmaxf(fmaxf(sred[4], sred[5]), fmaxf(sred[6], sred[7])));
        __syncthreads();
        float e = expf(s - m);
        float sum = e;
        #pragma unroll
        for (int o = 16; o; o >>= 1) sum += __shfl_xor_sync(0xFFFFFFFFu, sum, o);
        if ((t & 31) == 0) sred[t >> 5] = sum;
        __syncthreads();
        sum = sred[0] + sred[1] + sred[2] + sred[3] +
              sred[4] + sred[5] + sred[6] + sred[7];
        g_w[rg * NHEADS + h] = e / sum;
        __syncthreads();
    }
}

// ---------------- stage 5: attention pooling over new_nodes (already in out) ---------
__global__ void pool_kernel(float* __restrict__ out) {
    int b = blockIdx.x;
    int c = threadIdx.x;
    int h = c >> 6;
    const float* ob = out + (size_t)b * NNODE * FEAT_OUT;
    float acc = 0.f;
    for (int n = 0; n < NNODE; n++)
        acc += ob[n * FEAT_OUT + c] * g_w[((size_t)b * NNODE + n) * NHEADS + h];
    out[(size_t)MROWS * FEAT_OUT + (size_t)b * FEAT_OUT + c] = acc;
}

// ---------------- launch ----------------
extern "C" void kernel_launch(void* const* d_in, const int* in_sizes, int n_in,
                              void* d_out, int out_size) {
    const float* nodes = (const float*)d_in[0];
    const float* pe    = (const float*)d_in[1];
    const int*   mask  = (const int*)d_in[2];
    const float* globs = (const float*)d_in[3];
    const float* ln_g  = (const float*)d_in[4];
    const float* ln_b  = (const float*)d_in[5];
    const float* fw1   = (const float*)d_in[6];
    const float* fb1   = (const float*)d_in[7];
    const float* fw2   = (const float*)d_in[8];
    const float* fb2   = (const float*)d_in[9];
    const float* aw1   = (const float*)d_in[10];
    const float* ab1   = (const float*)d_in[11];
    const float* aw2   = (const float*)d_in[12];
    const float* ab2   = (const float*)d_in[13];
    float* out = (float*)d_out;

    float *inp, *h1, *fw1r, *aw1r, *fw2r;
    cudaGetSymbolAddress((void**)&inp,  g_inp);
    cudaGetSymbolAddress((void**)&h1,   g_h1);
    cudaGetSymbolAddress((void**)&fw1r, g_fw1r);
    cudaGetSymbolAddress((void**)&aw1r, g_aw1r);
    cudaGetSymbolAddress((void**)&fw2r, g_fw2r);

    cudaFuncSetAttribute(gemm1_kernel,
                         cudaFuncAttributeMaxDynamicSharedMemorySize, SMEM_BYTES);
    cudaFuncSetAttribute(gemm2_kernel,
                         cudaFuncAttributeMaxDynamicSharedMemorySize, SMEM_BYTES);
    cudaFuncSetAttribute(gemm3_kernel,
                         cudaFuncAttributeMaxDynamicSharedMemorySize, SMEM_BYTES);

    // ordered so GEMM-1 is the 4th launch (ncu capture slot)
    round_kernel<<<(IN_DIM * FEAT_HID + 255) / 256, 256>>>(fw1, fw1r, IN_DIM * FEAT_HID); // 1
    round_kernel<<<(IN_DIM * ATTN_HID + 255) / 256, 256>>>(aw1, aw1r, IN_DIM * ATTN_HID); // 2
    prep_kernel<<<MROWS, 128>>>(nodes, pe, globs, ln_g, ln_b);                            // 3

    gemm1_kernel<<<dim3(FEAT_HID / 128, MROWS / 128), 256, SMEM_BYTES>>>(                 // 4
        inp, fw1r, fb1, h1);
    gemm2_kernel<<<dim3(ATTN_HID / 128, MROWS / 128), 256, SMEM_BYTES>>>(                 // 5
        inp, aw1r, ab1, aw2);

    round_kernel<<<(FEAT_HID * FEAT_OUT + 255) / 256, 256>>>(fw2, fw2r,                   // 6
                                                             FEAT_HID * FEAT_OUT);
    gemm3_kernel<<<dim3(FEAT_OUT / 128, MROWS / 128), 256, SMEM_BYTES>>>(                 // 7
        h1, fw2r, fb2, nodes, mask, out);

    softmax_kernel<<<BATCH, 256>>>(mask, ab2);                                            // 8
    pool_kernel<<<BATCH, 256>>>(out);                                                     // 9
}